// round 15
// baseline (speedup 1.0000x reference)
#include <cuda_runtime.h>
#include <cstdint>

// Problem shape (fixed by the dataset problem)
#define B_  32
#define T_  1600
#define C_  1024
#define L_  128

// Device scratch (allocation-free rule: __device__ globals).
__device__ float g_emOdd[((size_t)B_ * T_ + 64) * 128];
__device__ float g_bll[B_ * T_];        // log-prob of blank per row (nats)
__device__ int   g_done[4][T_];         // per-(batch-group, t) completion flags

// ---------------------------------------------------------------------------
// Flag-zero kernel (runs before the fork each call)
// ---------------------------------------------------------------------------
__global__ void ctc_zero()
{
    int i = blockIdx.x * blockDim.x + threadIdx.x;
    if (i < 4 * T_) ((int*)g_done)[i] = 0;
}

// acquire-poll on a completion flag (R11-proven protocol)
__device__ __forceinline__ void waitrow(int g, int t)
{
    const int* fp = &g_done[g][t];
    int f;
    asm volatile("ld.acquire.gpu.global.b32 %0, [%1];" : "=r"(f) : "l"(fp));
    while (f == 0) {
        asm volatile("ld.acquire.gpu.global.b32 %0, [%1];" : "=r"(f) : "l"(fp));
    }
}

// ---------------------------------------------------------------------------
// Pass 1 (producer, own kernel & register budget): pure gather, T-MAJOR block
// order. Block ip covers rows r = 8*ip + warp -> t = r>>5 (constant within
// block), b = r&31 in batch-group ip&3. After its 8 rows: release flag.
// ---------------------------------------------------------------------------
__global__ void __launch_bounds__(256) ctc_pass1(
    const float* __restrict__ lp,       // [B,T,C]
    const int*   __restrict__ targets)  // [B,L]
{
    int ip   = blockIdx.x;
    int r    = 8 * ip + (threadIdx.x >> 5);
    int lane = threadIdx.x & 31;
    int t = r >> 5;
    int b = r & 31;
    size_t rowb = (size_t)b * T_ + t;

    const float* row = lp + rowb * C_;

    // 4 labels per lane -> odd states 8l+1..8l+7 ; ratios vs blank.
    const int4 tgv = *(const int4*)(targets + b * L_ + 4 * lane);
    float blv = row[0];                  // warp-broadcast load
    float e0 = row[tgv.x];
    float e1 = row[tgv.y];
    float e2 = row[tgv.z];
    float e3 = row[tgv.w];

    float4 outv;
    outv.x = __expf(e0 - blv);
    outv.y = __expf(e1 - blv);
    outv.z = __expf(e2 - blv);
    outv.w = __expf(e3 - blv);
    *(float4*)(g_emOdd + (rowb << 7) + (lane << 2)) = outv;

    if (lane == 0) g_bll[rowb] = blv;

    __syncthreads();                      // all 8 rows of this block written
    if (threadIdx.x == 0) {
        asm volatile("membar.gl;" ::: "memory");
        asm volatile("st.release.gpu.global.b32 [%0], %1;"
                     :: "l"(&g_done[ip & 3][ip >> 2]), "r"(1) : "memory");
    }
}

// ---------------------------------------------------------------------------
// Pass 2 (consumer): EXACT R14 alpha (numerics FROZEN), plus acquire-poll on
// each ring refill row and blsum reduction moved AFTER the main loop (all
// needed flags acquired by then; identical summation order).
// ---------------------------------------------------------------------------
__global__ void __launch_bounds__(32, 1) ctc_alpha(
    const int* __restrict__ targets,
    const int* __restrict__ in_len,
    const int* __restrict__ tgt_len,
    float*     __restrict__ out)
{
    int b    = blockIdx.x;
    int lane = threadIdx.x;
    int g    = b >> 3;

    int Tin = in_len[b];
    int Sb  = 2 * tgt_len[b] + 1;

    const size_t rowb = (size_t)b * T_;
    const float* bllb = g_bll + rowb;

    // skip flags for own odd states (label index li = 4*lane + j)
    const int* tg = targets + b * L_;
    int li = 4 * lane;
    float sk1 = (lane > 0 && tg[li] != tg[li - 1]) ? 1.f : 0.f;
    float sk3 = (tg[li + 1] != tg[li])     ? 1.f : 0.f;
    float sk5 = (tg[li + 2] != tg[li + 1]) ? 1.f : 0.f;
    float sk7 = (tg[li + 3] != tg[li + 2]) ? 1.f : 0.f;

    const float4* emO = (const float4*)g_emOdd;    // 32 float4 per row

    // t = 0 init (needs row 0 published)
    waitrow(g, 0);
    float o0=0.f,o1=0.f,o2=0.f,o3=0.f,o4=0.f,o5=0.f,o6=0.f,o7=0.f,o8=0.f;
    float eb0_l0 = __expf(bllb[0]);
    if (lane == 0) {
        o0 = eb0_l0;
        o1 = g_emOdd[rowb << 7] * eb0_l0;
    }
    int   lsc = 0;
    float ff  = 0.f;

    int nst = Tin - 1;   // steps t = 1..Tin-1 (Tin >= 800)

// Renorm boundary (every 4 steps) — FROZEN R10/R14 numerics, byte-for-byte.
#define BOUNDARY()                                                           \
    {                                                                        \
        float lm = fmaxf(fmaxf(fmaxf(o0,o1),fmaxf(o2,o3)),                   \
                         fmaxf(fmaxf(o4,o5),fmaxf(fmaxf(o6,o7),o8)));        \
        int elm   = __float_as_int(lm) >> 23;                                \
        int myabs = lsc + elm;                                               \
        int absL  = __shfl_up_sync(0xffffffffu, myabs, 1);                   \
        int absLL = __shfl_up_sync(0xffffffffu, myabs, 2);                   \
        if (lane < 1) absL  = myabs;                                         \
        if (lane < 2) absLL = -(1 << 29);                                    \
        int lscN  = ::max(myabs, absL)  - 127;                               \
        int lscNL = ::max(absL,  absLL) - 127;                               \
        int eo = ::min(::max(lsc - lscN + 127, 0), 254);                     \
        float sc = __int_as_float(eo << 23);                                 \
        int ef = ::min(::max(lscNL - lscN + 127, 0), 254);                   \
        ff = (lane == 0) ? 0.f : __int_as_float(ef << 23);                   \
        o0*=sc; o1*=sc; o2*=sc; o3*=sc; o4*=sc;                              \
        o5*=sc; o6*=sc; o7*=sc; o8*=sc;                                      \
        lsc = lscN;                                                          \
    }

// One time step: 17 fma-pipe ops + 1 shfl.
#define STEP(Ec)                                                             \
    {                                                                        \
        float h3 = __shfl_up_sync(0xffffffffu, o7, 1) * ff;                  \
        float n0 = o0 + h3;                                                  \
        float n1 = (Ec).x * fmaf(sk1, h3, o1 + o0);                          \
        float n2 = o2 + o1;                                                  \
        float n3 = (Ec).y * fmaf(sk3, o1, o3 + o2);                          \
        float n4 = o4 + o3;                                                  \
        float n5 = (Ec).z * fmaf(sk5, o3, o5 + o4);                          \
        float n6 = o6 + o5;                                                  \
        float n7 = (Ec).w * fmaf(sk7, o5, o7 + o6);                          \
        float n8 = o8 + o7;                                                  \
        o0=n0;o1=n1;o2=n2;o3=n3;o4=n4;o5=n5;o6=n6;o7=n7;o8=n8;               \
    }

    // emission ring, depth 16 (rows t = 1..16); poll each row's flag first
    float4 E[16];
#pragma unroll
    for (int i = 0; i < 16; ++i) {
        waitrow(g, 1 + i);
        E[i] = emO[(rowb + 1 + i) * 32 + lane];
    }

    const float4* pE = emO + (rowb + 17) * 32 + lane;   // refill base (row 1+k+16)

    int k = 0;
    while (k + 16 <= nst) {
#pragma unroll
        for (int q = 0; q < 4; ++q) {
            BOUNDARY();
#pragma unroll
            for (int j = 0; j < 4; ++j) {
                int u = 4 * q + j;
                int rr = k + u + 17;                        // row being refilled
                waitrow(g, rr < T_ ? rr : T_ - 1);
                float4 Ec = E[u];
                E[u] = pE[u * 32];                          // refill row 1+k+u+16
                asm volatile("prefetch.global.L2 [%0];"
                             :: "l"(pE + (u + 32) * 32));   // row 1+k+u+48 -> L2
                STEP(Ec);
            }
        }
        k  += 16;
        pE += 512;
    }

    // tail: <=4 steps per boundary, direct loads (rows already polled)
    while (k < nst) {
        BOUNDARY();
#pragma unroll 1
        for (int j = 0; j < 4 && k < nst; ++j, ++k) {
            float4 Ec = emO[(rowb + 1 + k) * 32 + lane];
            STEP(Ec);
        }
    }

    // deferred prologue reduction (rows 0..Tin-1 all acquired by now):
    // blsum = sum_{t in [1,Tin)} lp_blank — identical summation order.
    float bacc = 0.f;
    for (int t = lane; t < Tin; t += 32) bacc += bllb[t];
#pragma unroll
    for (int o = 16; o; o >>= 1) bacc += __shfl_xor_sync(0xffffffffu, bacc, o);
    float blsum = bacc - bllb[0];   // exclude t = 0

    // final readout: combine states Sb-1, Sb-2 in log space (per-lane scales)
    __shared__ float fin[257];
    __shared__ int   flsc[32];
    fin[8*lane+0]=o0; fin[8*lane+1]=o1; fin[8*lane+2]=o2; fin[8*lane+3]=o3;
    fin[8*lane+4]=o4; fin[8*lane+5]=o5; fin[8*lane+6]=o6; fin[8*lane+7]=o7;
    if (lane == 31) fin[256] = o8;
    flsc[lane] = lsc;
    __syncwarp();

    if (lane == 0) {
        int sA = Sb - 1, sB = Sb - 2;
        int lA_ = sA >> 3; if (lA_ > 31) lA_ = 31;
        int lB_ = sB >> 3; if (lB_ > 31) lB_ = 31;
        float  va = fin[sA], vb = fin[sB];
        double lA = (va > 0.f) ? (log2((double)va) + (double)flsc[lA_]) : -1e300;
        double lB = (vb > 0.f) ? (log2((double)vb) + (double)flsc[lB_]) : -1e300;
        double hi = (lA > lB) ? lA : lB;
        double lo = (lA > lB) ? lB : lA;
        double l2sum = hi + log2(1.0 + exp2(lo - hi));
        double llh = 0.6931471805599453 * l2sum + (double)blsum;
        out[b] = (float)(-llh);     // normalizer of log_softmax rows == 0
    }
#undef BOUNDARY
#undef STEP
}

// ---------------------------------------------------------------------------
// Launch: fork the capture stream with events so pass1 (producer) runs
// concurrently with alpha (consumer), each with its own register budget.
// Stream/event handles are created per call and intentionally not destroyed
// (host-side only; kernel_launch runs host code just twice).
// ---------------------------------------------------------------------------
extern "C" void kernel_launch(void* const* d_in, const int* in_sizes, int n_in,
                              void* d_out, int out_size)
{
    const float* lp      = (const float*)d_in[0];
    const int*   targets = (const int*)d_in[1];
    const int*   ilen    = (const int*)d_in[2];
    const int*   tlen    = (const int*)d_in[3];
    float*       out     = (float*)d_out;
    (void)in_sizes; (void)n_in; (void)out_size;

    // Identify the stream our <<<>>>-default launches land on (the one being
    // captured, when capturing): per-thread if it is actively capturing,
    // otherwise the legacy default stream.
    cudaStreamCaptureStatus st = cudaStreamCaptureStatusNone;
    cudaStreamIsCapturing(cudaStreamPerThread, &st);
    cudaStream_t s0 = (st == cudaStreamCaptureStatusActive)
                    ? cudaStreamPerThread : cudaStreamLegacy;

    cudaStream_t s2;
    cudaStreamCreateWithFlags(&s2, cudaStreamNonBlocking);
    cudaEvent_t e1, e2;
    cudaEventCreateWithFlags(&e1, cudaEventDisableTiming);
    cudaEventCreateWithFlags(&e2, cudaEventDisableTiming);

    ctc_zero<<<(4 * T_ + 255) / 256, 256, 0, s0>>>();

    cudaEventRecord(e1, s0);
    cudaStreamWaitEvent(s2, e1, 0);

    ctc_pass1<<<(B_ * T_) / 8, 256, 0, s2>>>(lp, targets);   // producer
    cudaEventRecord(e2, s2);

    ctc_alpha<<<B_, 32, 0, s0>>>(targets, ilen, tlen, out);  // consumer

    cudaStreamWaitEvent(s0, e2, 0);                          // join
}

// round 16
// speedup vs baseline: 4.0061x; 4.0061x over previous
#include <cuda_runtime.h>
#include <cstdint>

// Problem shape (fixed by the dataset problem)
#define B_  32
#define T_  1600
#define C_  1024
#define L_  128

// Device scratch (allocation-free rule: __device__ globals).
__device__ float g_emOdd[((size_t)B_ * T_ + 64) * 128];
__device__ float g_bll[B_ * T_];        // log-prob of blank per row (nats)
__device__ int   g_done[4][T_];         // per-(batch-group, t) completion flags

// ---------------------------------------------------------------------------
// Flag-zero kernel (runs before the fork each call)
// ---------------------------------------------------------------------------
__global__ void ctc_zero()
{
    int i = blockIdx.x * blockDim.x + threadIdx.x;
    if (i < 4 * T_) ((int*)g_done)[i] = 0;
}

// Vectorized flag check: verify 16 consecutive row flags [t0, t0+15] (capped
// at tmax) in ONE L2 round trip. Warp-converged; retries only while the
// producer hasn't published yet.
__device__ __forceinline__ void wait16(int g, int t0, int tmax)
{
    int t = t0 + (threadIdx.x & 15);
    t = (t < tmax) ? t : tmax;
    if (t < 0) t = 0;
    const int* fp = &g_done[g][t];
    while (true) {
        int f;
        asm volatile("ld.acquire.gpu.global.b32 %0, [%1];" : "=r"(f) : "l"(fp));
        if (__all_sync(0xffffffffu, f != 0)) break;
    }
}

// ---------------------------------------------------------------------------
// Pass 1 (producer, own kernel & register budget): pure gather, T-MAJOR block
// order. Block ip covers rows r = 8*ip + warp -> t = ip>>2 (constant within
// block), batch-group ip&3. After its 8 rows: release flag.
// ---------------------------------------------------------------------------
__global__ void __launch_bounds__(256) ctc_pass1(
    const float* __restrict__ lp,       // [B,T,C]
    const int*   __restrict__ targets)  // [B,L]
{
    int ip   = blockIdx.x;
    int r    = 8 * ip + (threadIdx.x >> 5);
    int lane = threadIdx.x & 31;
    int t = r >> 5;
    int b = r & 31;
    size_t rowb = (size_t)b * T_ + t;

    const float* row = lp + rowb * C_;

    // 4 labels per lane -> odd states 8l+1..8l+7 ; ratios vs blank.
    const int4 tgv = *(const int4*)(targets + b * L_ + 4 * lane);
    float blv = row[0];                  // warp-broadcast load
    float e0 = row[tgv.x];
    float e1 = row[tgv.y];
    float e2 = row[tgv.z];
    float e3 = row[tgv.w];

    float4 outv;
    outv.x = __expf(e0 - blv);
    outv.y = __expf(e1 - blv);
    outv.z = __expf(e2 - blv);
    outv.w = __expf(e3 - blv);
    *(float4*)(g_emOdd + (rowb << 7) + (lane << 2)) = outv;

    if (lane == 0) g_bll[rowb] = blv;

    __syncthreads();                      // all 8 rows of this block written
    if (threadIdx.x == 0) {
        asm volatile("membar.gl;" ::: "memory");
        asm volatile("st.release.gpu.global.b32 [%0], %1;"
                     :: "l"(&g_done[ip & 3][ip >> 2]), "r"(1) : "memory");
    }
}

// ---------------------------------------------------------------------------
// Pass 2 (consumer): EXACT R14 alpha (numerics FROZEN). Flag verification is
// amortized: one wait16 per 16-step chunk, issued one chunk ahead of use.
// ---------------------------------------------------------------------------
__global__ void __launch_bounds__(32, 1) ctc_alpha(
    const int* __restrict__ targets,
    const int* __restrict__ in_len,
    const int* __restrict__ tgt_len,
    float*     __restrict__ out)
{
    int b    = blockIdx.x;
    int lane = threadIdx.x;
    int g    = b >> 3;

    int Tin = in_len[b];
    int Sb  = 2 * tgt_len[b] + 1;

    const size_t rowb = (size_t)b * T_;
    const float* bllb = g_bll + rowb;

    // skip flags for own odd states (label index li = 4*lane + j)
    const int* tg = targets + b * L_;
    int li = 4 * lane;
    float sk1 = (lane > 0 && tg[li] != tg[li - 1]) ? 1.f : 0.f;
    float sk3 = (tg[li + 1] != tg[li])     ? 1.f : 0.f;
    float sk5 = (tg[li + 2] != tg[li + 1]) ? 1.f : 0.f;
    float sk7 = (tg[li + 3] != tg[li + 2]) ? 1.f : 0.f;

    const float4* emO = (const float4*)g_emOdd;    // 32 float4 per row

    // verify rows 0..47 up front (producer leads after ~1-2us)
    wait16(g, 0,  T_ - 1);
    wait16(g, 16, T_ - 1);
    wait16(g, 32, T_ - 1);

    // t = 0 init
    float o0=0.f,o1=0.f,o2=0.f,o3=0.f,o4=0.f,o5=0.f,o6=0.f,o7=0.f,o8=0.f;
    float eb0_l0 = __expf(bllb[0]);
    if (lane == 0) {
        o0 = eb0_l0;
        o1 = g_emOdd[rowb << 7] * eb0_l0;
    }
    int   lsc = 0;
    float ff  = 0.f;

    int nst = Tin - 1;   // steps t = 1..Tin-1 (Tin >= 800)

// Renorm boundary (every 4 steps) — FROZEN R10/R14 numerics, byte-for-byte.
#define BOUNDARY()                                                           \
    {                                                                        \
        float lm = fmaxf(fmaxf(fmaxf(o0,o1),fmaxf(o2,o3)),                   \
                         fmaxf(fmaxf(o4,o5),fmaxf(fmaxf(o6,o7),o8)));        \
        int elm   = __float_as_int(lm) >> 23;                                \
        int myabs = lsc + elm;                                               \
        int absL  = __shfl_up_sync(0xffffffffu, myabs, 1);                   \
        int absLL = __shfl_up_sync(0xffffffffu, myabs, 2);                   \
        if (lane < 1) absL  = myabs;                                         \
        if (lane < 2) absLL = -(1 << 29);                                    \
        int lscN  = ::max(myabs, absL)  - 127;                               \
        int lscNL = ::max(absL,  absLL) - 127;                               \
        int eo = ::min(::max(lsc - lscN + 127, 0), 254);                     \
        float sc = __int_as_float(eo << 23);                                 \
        int ef = ::min(::max(lscNL - lscN + 127, 0), 254);                   \
        ff = (lane == 0) ? 0.f : __int_as_float(ef << 23);                   \
        o0*=sc; o1*=sc; o2*=sc; o3*=sc; o4*=sc;                              \
        o5*=sc; o6*=sc; o7*=sc; o8*=sc;                                      \
        lsc = lscN;                                                          \
    }

// One time step: 17 fma-pipe ops + 1 shfl.
#define STEP(Ec)                                                             \
    {                                                                        \
        float h3 = __shfl_up_sync(0xffffffffu, o7, 1) * ff;                  \
        float n0 = o0 + h3;                                                  \
        float n1 = (Ec).x * fmaf(sk1, h3, o1 + o0);                          \
        float n2 = o2 + o1;                                                  \
        float n3 = (Ec).y * fmaf(sk3, o1, o3 + o2);                          \
        float n4 = o4 + o3;                                                  \
        float n5 = (Ec).z * fmaf(sk5, o3, o5 + o4);                          \
        float n6 = o6 + o5;                                                  \
        float n7 = (Ec).w * fmaf(sk7, o5, o7 + o6);                          \
        float n8 = o8 + o7;                                                  \
        o0=n0;o1=n1;o2=n2;o3=n3;o4=n4;o5=n5;o6=n6;o7=n7;o8=n8;               \
    }

    // emission ring, depth 16 (rows t = 1..16, verified above)
    float4 E[16];
#pragma unroll
    for (int i = 0; i < 16; ++i) E[i] = emO[(rowb + 1 + i) * 32 + lane];

    const float4* pE = emO + (rowb + 17) * 32 + lane;   // refill base (row 1+k+16)

    int k = 0;
    while (k + 16 <= nst) {
        // verify rows k+33..k+48 (needed by NEXT chunk's refills) —
        // issued here so its latency hides under this chunk's compute.
        wait16(g, k + 33, T_ - 1);
#pragma unroll
        for (int q = 0; q < 4; ++q) {
            BOUNDARY();
#pragma unroll
            for (int j = 0; j < 4; ++j) {
                int u = 4 * q + j;
                float4 Ec = E[u];
                E[u] = pE[u * 32];                          // refill row 1+k+u+16
                asm volatile("prefetch.global.L2 [%0];"
                             :: "l"(pE + (u + 32) * 32));   // row 1+k+u+48 -> L2
                STEP(Ec);
            }
        }
        k  += 16;
        pE += 512;
    }

    // tail: <=4 steps per boundary, direct loads (rows <= nst all verified)
    while (k < nst) {
        BOUNDARY();
#pragma unroll 1
        for (int j = 0; j < 4 && k < nst; ++j, ++k) {
            float4 Ec = emO[(rowb + 1 + k) * 32 + lane];
            STEP(Ec);
        }
    }

    // deferred prologue reduction (rows 0..Tin-1 all verified by now):
    // blsum = sum_{t in [1,Tin)} lp_blank — identical summation order.
    float bacc = 0.f;
    for (int t = lane; t < Tin; t += 32) bacc += bllb[t];
#pragma unroll
    for (int o = 16; o; o >>= 1) bacc += __shfl_xor_sync(0xffffffffu, bacc, o);
    float blsum = bacc - bllb[0];   // exclude t = 0

    // final readout: combine states Sb-1, Sb-2 in log space (per-lane scales)
    __shared__ float fin[257];
    __shared__ int   flsc[32];
    fin[8*lane+0]=o0; fin[8*lane+1]=o1; fin[8*lane+2]=o2; fin[8*lane+3]=o3;
    fin[8*lane+4]=o4; fin[8*lane+5]=o5; fin[8*lane+6]=o6; fin[8*lane+7]=o7;
    if (lane == 31) fin[256] = o8;
    flsc[lane] = lsc;
    __syncwarp();

    if (lane == 0) {
        int sA = Sb - 1, sB = Sb - 2;
        int lA_ = sA >> 3; if (lA_ > 31) lA_ = 31;
        int lB_ = sB >> 3; if (lB_ > 31) lB_ = 31;
        float  va = fin[sA], vb = fin[sB];
        double lA = (va > 0.f) ? (log2((double)va) + (double)flsc[lA_]) : -1e300;
        double lB = (vb > 0.f) ? (log2((double)vb) + (double)flsc[lB_]) : -1e300;
        double hi = (lA > lB) ? lA : lB;
        double lo = (lA > lB) ? lB : lA;
        double l2sum = hi + log2(1.0 + exp2(lo - hi));
        double llh = 0.6931471805599453 * l2sum + (double)blsum;
        out[b] = (float)(-llh);     // normalizer of log_softmax rows == 0
    }
#undef BOUNDARY
#undef STEP
}

// ---------------------------------------------------------------------------
// Launch: fork the capture stream with events so pass1 (producer) runs
// concurrently with alpha (consumer), each with its own register budget.
// ---------------------------------------------------------------------------
extern "C" void kernel_launch(void* const* d_in, const int* in_sizes, int n_in,
                              void* d_out, int out_size)
{
    const float* lp      = (const float*)d_in[0];
    const int*   targets = (const int*)d_in[1];
    const int*   ilen    = (const int*)d_in[2];
    const int*   tlen    = (const int*)d_in[3];
    float*       out     = (float*)d_out;
    (void)in_sizes; (void)n_in; (void)out_size;

    cudaStreamCaptureStatus st = cudaStreamCaptureStatusNone;
    cudaStreamIsCapturing(cudaStreamPerThread, &st);
    cudaStream_t s0 = (st == cudaStreamCaptureStatusActive)
                    ? cudaStreamPerThread : cudaStreamLegacy;

    cudaStream_t s2;
    cudaStreamCreateWithFlags(&s2, cudaStreamNonBlocking);
    cudaEvent_t e1, e2;
    cudaEventCreateWithFlags(&e1, cudaEventDisableTiming);
    cudaEventCreateWithFlags(&e2, cudaEventDisableTiming);

    ctc_zero<<<(4 * T_ + 255) / 256, 256, 0, s0>>>();

    cudaEventRecord(e1, s0);
    cudaStreamWaitEvent(s2, e1, 0);

    ctc_pass1<<<(B_ * T_) / 8, 256, 0, s2>>>(lp, targets);   // producer
    cudaEventRecord(e2, s2);

    ctc_alpha<<<B_, 32, 0, s0>>>(targets, ilen, tlen, out);  // consumer

    cudaStreamWaitEvent(s0, e2, 0);                          // join
}